// round 14
// baseline (speedup 1.0000x reference)
#include <cuda_runtime.h>
#include <cuda_bf16.h>

// Problem constants (fixed shapes from setup_inputs)
constexpr int B    = 4;
constexpr int S    = 2048;
constexpr int N    = B * S;        // 8192
constexpr int KNEG = 4;
constexpr int NK   = N * KNEG;     // 32768
constexpr int WMAX = 16;

#define SOFT 1e-6f
#define EPSF 1e-9f
#define CUT2 0.01f

constexpr int T2      = 32;              // 64-row tiles per batch
constexpr int TASKS_B = T2 * (T2 + 1) / 2;     // 528
constexpr int NTASK   = TASKS_B * B;     // 2112 tile-pair tasks
constexpr int NHALF   = NTASK * 2;       // 4224 half-tasks (16 steps each)
constexpr int TPB     = 512;             // 16 warps
constexpr int TOTAL   = 296;             // 2 * 148 SMs -> single wave
constexpr int NWARPS  = TOTAL * (TPB / 32);    // 4736
constexpr int NLOSSW  = NWARPS - NHALF;  // 512 loss warps

// partial forces: [B*T2 tiles][T2 partners][2 halves][64 rows] float2 = 4 MB
__device__ __align__(16) float2 g_acc[B * T2 * T2 * 2 * 64];
__device__ __align__(16) float  g_lpart[NLOSSW * 8];
__device__ unsigned int g_bar;    // arrive counter (zero-init)
__device__ unsigned int g_bar2;   // exit counter for replay-safe reset

// ---------------- raw approx MUFU ---------------------------------------
__device__ __forceinline__ float rsq(float x) {
    float r; asm("rsqrt.approx.f32 %0, %1;" : "=f"(r) : "f"(x)); return r;
}
__device__ __forceinline__ float rcp(float x) {
    float r; asm("rcp.approx.f32 %0, %1;" : "=f"(r) : "f"(x)); return r;
}

// ---------------------------------------------------------------------------
__device__ __forceinline__ float mind2_row(const float4 a, const float4 b4,
                                           const float* __restrict__ wsh, int W)
{
    float best = 3.4e38f;
    for (int w = 0; w < W; w++) {
        const float* wc = &wsh[w * 8];
        float d = 0.0f, t;
        t = a.x  - wc[0]; d = fmaf(t, t, d);
        t = a.y  - wc[1]; d = fmaf(t, t, d);
        t = a.z  - wc[2]; d = fmaf(t, t, d);
        t = a.w  - wc[3]; d = fmaf(t, t, d);
        t = b4.x - wc[4]; d = fmaf(t, t, d);
        t = b4.y - wc[5]; d = fmaf(t, t, d);
        t = b4.z - wc[6]; d = fmaf(t, t, d);
        t = b4.w - wc[7]; d = fmaf(t, t, d);
        best = fminf(best, d);
    }
    return best;   // min(dist)^2 == min(dist^2)
}

// ---------------------------------------------------------------------------
// One persistent kernel, grid 296 x 512, 2 CTAs/SM (single wave; spin barrier
// deadlock-free). Warp role by block-strided global id g = bid + 296*warp:
//   g < NHALF:   force half-task (task g>>1, butterfly steps [16*(g&1), +16))
//   else:        loss warp (per-warp partial sums, no intra-block sync)
// Phase B after grid barrier: blocks [0,128) reduce g_acc; block 128 loss final.
// ---------------------------------------------------------------------------
__global__ __launch_bounds__(TPB, 2)
void physics_kernel(const float* __restrict__ pos,
                    const float* __restrict__ mass,
                    const float* __restrict__ vel,
                    const float* __restrict__ pos8,
                    const float* __restrict__ pp2d,
                    const float* __restrict__ pp8,
                    const float* __restrict__ pmass,
                    const float* __restrict__ np2d,
                    const float* __restrict__ np8,
                    const float* __restrict__ nmass,
                    const float* __restrict__ emass,
                    const float* __restrict__ wells,
                    const float* __restrict__ G_,
                    const float* __restrict__ rep_,
                    const float* __restrict__ ws_,
                    int W,
                    float* __restrict__ out)
{
    __shared__ float wsh[WMAX * 8];
    __shared__ __align__(16) float2 sredB[8][64];   // phase-B partial sums

    const int tid  = threadIdx.x;
    const int lane = tid & 31;
    const int warp = tid >> 5;
    const float Gp = fmaxf(G_[0], 0.0f);

    // wells to smem in every block (loss warps live in all blocks)
    if (tid < W * 8) wsh[tid] = wells[tid];
    __syncthreads();

    const int g = blockIdx.x + TOTAL * warp;   // block-strided warp id

    // ============================ PHASE A ============================
    if (g < NHALF) {
        // ---- force half-task ----
        const float reps = fmaxf(rep_[0], 0.0f);
        const float c1   = -10.0f * reps;
        const float c0   = reps;
        const float2* pos2 = (const float2*)pos;

        const int task = g >> 1;
        const int k0   = (g & 1) * 16;
        const int b    = task / TASKS_B;
        const int r    = task - b * TASKS_B;
        // unrank r -> (I <= J) over T2=32: row I has (32-I) entries
        int I = (int)(32.5f - sqrtf(fmaf(-2.0f, (float)r, 1056.25f)));
        while ((I + 1) * T2 - ((I + 1) * I) / 2 <= r) I++;
        while (I * T2 - (I * (I - 1)) / 2 > r) I--;
        const int J = I + (r - (I * T2 - (I * (I - 1)) / 2));
        const bool diag = (I == J);

        const int ia = b * S + I * 64 + lane;       // i originals
        const int jc = b * S + J * 64 + lane;       // j residents
        const float2 pa = pos2[ia];
        const float2 pb = pos2[ia + 32];
        const float2 pc = pos2[jc];
        const float2 pd = pos2[jc + 32];
        const float xa0 = pa.x, ya0 = pa.y;
        const float xb0 = pb.x, yb0 = pb.y;
        const float xc = pc.x, yc = pc.y;
        const float xd = pd.x, yd = pd.y;
        const float ga0 = -Gp * mass[ia];
        const float gb0 = -Gp * mass[ia + 32];
        const float mc = mass[jc];
        const float md = mass[jc + 32];

        float fax = 0.f, fay = 0.f, fbx = 0.f, fby = 0.f;   // fi (routed back)
        float fcx = 0.f, fcy = 0.f, fdx_ = 0.f, fdy_ = 0.f; // fj (resident)

#pragma unroll 4
        for (int k = k0; k < k0 + 16; k++) {
            const float xa = __shfl_xor_sync(0xffffffffu, xa0, k);
            const float ya = __shfl_xor_sync(0xffffffffu, ya0, k);
            const float ga = __shfl_xor_sync(0xffffffffu, ga0, k);
            const float xb = __shfl_xor_sync(0xffffffffu, xb0, k);
            const float yb = __shfl_xor_sync(0xffffffffu, yb0, k);
            const float gb = __shfl_xor_sync(0xffffffffu, gb0, k);

            const float dxac = xc - xa, dyac = yc - ya;
            const float dxad = xd - xa, dyad = yd - ya;
            const float dxbc = xc - xb, dybc = yc - yb;
            const float dxbd = xd - xb, dybd = yd - yb;

            const float d2ac = fmaf(dxac, dxac, fmaf(dyac, dyac, SOFT));
            const float d2ad = fmaf(dxad, dxad, fmaf(dyad, dyad, SOFT));
            const float d2bc = fmaf(dxbc, dxbc, fmaf(dybc, dybc, SOFT));
            const float d2bd = fmaf(dxbd, dxbd, fmaf(dybd, dybd, SOFT));

            const float uac = rsq(d2ac);
            const float uad = rsq(d2ad);
            const float ubc = rsq(d2bc);
            const float ubd = rsq(d2bd);

            float wac = (ga * mc) * ((uac * uac) * uac);
            float wad = (ga * md) * ((uad * uad) * uad);
            float wbc = (gb * mc) * ((ubc * ubc) * ubc);
            float wbd = (gb * md) * ((ubd * ubd) * ubd);

            const float mn = fminf(fminf(d2ac, d2ad), fminf(d2bc, d2bd));
            if (__any_sync(0xffffffffu, mn < CUT2)) {
                {
                    const float d = d2ac * uac;
                    const float tt = fmaxf(fmaf(d, c1, c0), 0.0f);
                    wac = fmaf(tt * rcp(fmaf(d2ac, d, EPSF)), uac, wac);
                }
                {
                    const float d = d2ad * uad;
                    const float tt = fmaxf(fmaf(d, c1, c0), 0.0f);
                    wad = fmaf(tt * rcp(fmaf(d2ad, d, EPSF)), uad, wad);
                }
                {
                    const float d = d2bc * ubc;
                    const float tt = fmaxf(fmaf(d, c1, c0), 0.0f);
                    wbc = fmaf(tt * rcp(fmaf(d2bc, d, EPSF)), ubc, wbc);
                }
                {
                    const float d = d2bd * ubd;
                    const float tt = fmaxf(fmaf(d, c1, c0), 0.0f);
                    wbd = fmaf(tt * rcp(fmaf(d2bd, d, EPSF)), ubd, wbd);
                }
            }

            const float wdxac = wac * dxac, wdyac = wac * dyac;
            const float wdxad = wad * dxad, wdyad = wad * dyad;
            const float wdxbc = wbc * dxbc, wdybc = wbc * dybc;
            const float wdxbd = wbd * dxbd, wdybd = wbd * dybd;

            // force on j rows (resident): fj -= w*dx
            fcx -= wdxac + wdxbc;
            fcy -= wdyac + wdybc;
            fdx_ -= wdxad + wdxbd;
            fdy_ -= wdyad + wdybd;

            // route fi sums back to the owning lane (same bfly)
            fax += __shfl_xor_sync(0xffffffffu, wdxac + wdxad, k);
            fay += __shfl_xor_sync(0xffffffffu, wdyac + wdyad, k);
            fbx += __shfl_xor_sync(0xffffffffu, wdxbc + wdxbd, k);
            fby += __shfl_xor_sync(0xffffffffu, wdybc + wdybd, k);
        }

        const int half = g & 1;
        const int baseI = (((b * T2 + I) * T2 + J) * 2 + half) * 64;
        g_acc[baseI + lane]      = make_float2(fax, fay);
        g_acc[baseI + 32 + lane] = make_float2(fbx, fby);
        if (!diag) {
            const int baseJ = (((b * T2 + J) * T2 + I) * 2 + half) * 64;
            g_acc[baseJ + lane]      = make_float2(fcx, fcy);
            g_acc[baseJ + 32 + lane] = make_float2(fdx_, fdy_);
        }
    } else {
        // ---- loss warp (per-warp partials; no block sync needed) ----
        const int lw = g - NHALF;              // 0..NLOSSW-1
        float s1 = 0.f, s2 = 0.f, s3 = 0.f, s4 = 0.f, s5 = 0.f, s6 = 0.f, s7 = 0.f;
        const int stride = NLOSSW * 32;        // 16384

        for (int i = lw * 32 + lane; i < N; i += stride) {
            float2 p = ((const float2*)pos)[i];
            float2 q = ((const float2*)pp2d)[i];
            float dx = p.x - q.x, dy = p.y - q.y;
            float d2 = fmaf(dx, dx, dy * dy);
            float m = mass[i];
            s1 = fmaf(m * pmass[i], rsq(d2), s1);   // eps vs dist: <=1e-6 rel
            s6 += m;
            float2 v = ((const float2*)vel)[i];
            s7 = fmaf(v.x, v.x, fmaf(v.y, v.y, s7));

            float4 a  = ((const float4*)pos8)[i * 2];
            float4 b4 = ((const float4*)pos8)[i * 2 + 1];
            s3 += mind2_row(a, b4, wsh, W);
            a  = ((const float4*)pp8)[i * 2];
            b4 = ((const float4*)pp8)[i * 2 + 1];
            s4 += mind2_row(a, b4, wsh, W);
        }

        for (int n = lw * 32 + lane; n < NK; n += stride) {
            float2 p = ((const float2*)pos)[n / KNEG];
            float2 q = ((const float2*)np2d)[n];
            float dx = p.x - q.x, dy = p.y - q.y;
            float d2 = fmaf(dx, dx, dy * dy);
            s2 = fmaf(emass[n] * nmass[n], rsq(d2), s2);

            float4 a  = ((const float4*)np8)[n * 2];
            float4 b4 = ((const float4*)np8)[n * 2 + 1];
            s5 += mind2_row(a, b4, wsh, W);
        }

        float vals[7] = {s1, s2, s3, s4, s5, s6, s7};
#pragma unroll
        for (int k = 0; k < 7; k++) {
#pragma unroll
            for (int off = 16; off > 0; off >>= 1)
                vals[k] += __shfl_down_sync(0xffffffffu, vals[k], off);
        }
        if (lane == 0) {
#pragma unroll
            for (int k = 0; k < 7; k++) g_lpart[lw * 8 + k] = vals[k];
        }
    }

    // ======================= GRID BARRIER =======================
    __syncthreads();
    if (tid == 0) {
        __threadfence();                       // publish g_acc / g_lpart
        atomicAdd(&g_bar, 1u);
        while (*(volatile unsigned int*)&g_bar < (unsigned)TOTAL) { }
        __threadfence();                       // acquire (L1 invalidate)
    }
    __syncthreads();

    // ============================ PHASE B ============================
    if (blockIdx.x < B * T2) {
        // one CTA per 64-row tile: sum its 64 partner-half slots (coalesced)
        const float2* basep = g_acc + blockIdx.x * (T2 * 2 * 64);
        const int c  = tid & 63;          // row within tile
        const int r0 = tid >> 6;          // 0..7
        float fx = 0.0f, fy = 0.0f;
#pragma unroll
        for (int k = 0; k < 8; k++) {
            const float2 v = basep[(r0 + 8 * k) * 64 + c];
            fx += v.x;
            fy += v.y;
        }
        sredB[r0][c] = make_float2(fx, fy);
        __syncthreads();
        if (r0 == 0) {
            float sx = 0.0f, sy = 0.0f;
#pragma unroll
            for (int q = 0; q < 8; q++) {
                sx += sredB[q][c].x;
                sy += sredB[q][c].y;
            }
            ((float2*)out)[blockIdx.x * 64 + c] = make_float2(sx, sy);
        }
    }

    if (blockIdx.x == B * T2 && warp == 0) {   // block 128: loss final
        float s[7];
#pragma unroll
        for (int k = 0; k < 7; k++) {
            float v = 0.0f;
#pragma unroll
            for (int q = 0; q < NLOSSW / 32; q++)      // 16 strided entries
                v += g_lpart[(lane + 32 * q) * 8 + k];
#pragma unroll
            for (int off = 16; off > 0; off >>= 1)
                v += __shfl_down_sync(0xffffffffu, v, off);
            s[k] = v;
        }
        if (lane == 0) {
            const float ws = fmaxf(ws_[0], 0.0f);
            const float S1 = s[0], S2 = s[1], S3 = s[2], S4 = s[3],
                        S5 = s[4], S6 = s[5], S7 = s[6];
            const float U_pos = -Gp * (S1 / (float)N) +
                                ws * (S3 + S4) / (2.0f * (float)N);
            const float U_neg = -Gp * (S2 / (float)NK) +
                                ws * ((float)KNEG * S3 + S5) / (2.0f * (float)NK);
            // entropy term cancels in F_pos - F_neg
            const float fe = fmaxf(1.0f + U_pos - U_neg, 0.0f);
            const float ke = 1e-3f * 0.5f * (S6 / (float)N) * (S7 / (float)N);
            out[N * 2] = fe + ke;
        }
    }

    // ---- replay-safe reset: last block to exit zeroes both counters.
    __syncthreads();
    if (tid == 0) {
        unsigned t2 = atomicAdd(&g_bar2, 1u);
        if (t2 == (unsigned)(TOTAL - 1)) {
            g_bar  = 0;
            g_bar2 = 0;
        }
    }
}

// ---------------------------------------------------------------------------
extern "C" void kernel_launch(void* const* d_in, const int* in_sizes, int n_in,
                              void* d_out, int out_size)
{
    const float* positions_2d = (const float*)d_in[0];
    const float* masses       = (const float*)d_in[1];
    const float* vel_2d       = (const float*)d_in[2];
    const float* pos_8d       = (const float*)d_in[3];
    const float* pos_pos_2d   = (const float*)d_in[4];
    const float* pos_pos_8d   = (const float*)d_in[5];
    const float* positive_m   = (const float*)d_in[6];
    const float* neg_pos_2d   = (const float*)d_in[7];
    const float* neg_pos_8d   = (const float*)d_in[8];
    const float* neg_masses   = (const float*)d_in[9];
    const float* exp_masses   = (const float*)d_in[10];
    const float* G            = (const float*)d_in[11];
    const float* rep_strength = (const float*)d_in[12];
    const float* well_centers = (const float*)d_in[13];
    const float* well_str     = (const float*)d_in[14];
    // temperature (15) / entropy_coeff (16) unused: entropy cancels.

    const int W = in_sizes[13] / 8;
    float* out = (float*)d_out;

    physics_kernel<<<TOTAL, TPB>>>(positions_2d, masses, vel_2d, pos_8d,
                                   pos_pos_2d, pos_pos_8d, positive_m,
                                   neg_pos_2d, neg_pos_8d, neg_masses,
                                   exp_masses, well_centers,
                                   G, rep_strength, well_str, W, out);
}

// round 15
// speedup vs baseline: 1.0645x; 1.0645x over previous
#include <cuda_runtime.h>
#include <cuda_bf16.h>

// Problem constants (fixed shapes from setup_inputs)
constexpr int B    = 4;
constexpr int S    = 2048;
constexpr int N    = B * S;        // 8192
constexpr int KNEG = 4;
constexpr int NK   = N * KNEG;     // 32768
constexpr int WMAX = 16;

#define SOFT 1e-6f
#define EPSF 1e-9f
#define CUT2 0.01f

constexpr int T      = 64;               // 32-row tiles per batch
constexpr int TASKS_PER_B = T * (T + 1) / 2;   // 2080
constexpr int TPB    = 512;              // 16 warps
constexpr int FBLK   = 260;              // 260*16 = 4160 warps -> 2 tasks each
constexpr int LBL    = 36;               // loss partial blocks
constexpr int TOTAL  = FBLK + LBL;       // 296

// partial forces: [B*T tiles][64 partner slots][32 lanes] float2 = 4 MB
__device__ __align__(16) float2 g_acc[B * T * T * 32];
__device__ __align__(16) float  g_lpart[LBL * 8];

// ---------------- raw approx MUFU ---------------------------------------
__device__ __forceinline__ float rsq(float x) {
    float r; asm("rsqrt.approx.f32 %0, %1;" : "=f"(r) : "f"(x)); return r;
}
__device__ __forceinline__ float rcp(float x) {
    float r; asm("rcp.approx.f32 %0, %1;" : "=f"(r) : "f"(x)); return r;
}

// ---------------------------------------------------------------------------
__device__ __forceinline__ float mind2_row(const float4 a, const float4 b4,
                                           const float* __restrict__ wsh, int W)
{
    float best = 3.4e38f;
    for (int w = 0; w < W; w++) {
        const float* wc = &wsh[w * 8];
        float d = 0.0f, t;
        t = a.x  - wc[0]; d = fmaf(t, t, d);
        t = a.y  - wc[1]; d = fmaf(t, t, d);
        t = a.z  - wc[2]; d = fmaf(t, t, d);
        t = a.w  - wc[3]; d = fmaf(t, t, d);
        t = b4.x - wc[4]; d = fmaf(t, t, d);
        t = b4.y - wc[5]; d = fmaf(t, t, d);
        t = b4.z - wc[6]; d = fmaf(t, t, d);
        t = b4.w - wc[7]; d = fmaf(t, t, d);
        best = fminf(best, d);
    }
    return best;   // min(dist)^2 == min(dist^2)
}

// ---------------------------------------------------------------------------
// Kernel 1 (identical to the round-9 version that measured ~10us wall).
// Blocks [0,FBLK): symmetric force tile-pairs, one warp per task, two tasks
// per warp. Blocks [FBLK,TOTAL): loss partials.
// ---------------------------------------------------------------------------
__global__ __launch_bounds__(TPB)
void force_loss_kernel(const float* __restrict__ pos,
                       const float* __restrict__ mass,
                       const float* __restrict__ vel,
                       const float* __restrict__ pos8,
                       const float* __restrict__ pp2d,
                       const float* __restrict__ pp8,
                       const float* __restrict__ pmass,
                       const float* __restrict__ np2d,
                       const float* __restrict__ np8,
                       const float* __restrict__ nmass,
                       const float* __restrict__ emass,
                       const float* __restrict__ wells,
                       const float* __restrict__ G_,
                       const float* __restrict__ rep_,
                       int W)
{
    const int tid  = threadIdx.x;
    const int lane = tid & 31;
    const int warp = tid >> 5;
    const float Gp = fmaxf(G_[0], 0.0f);

    if (blockIdx.x < FBLK) {
        // =================== SYMMETRIC FORCE ===================
        const float reps = fmaxf(rep_[0], 0.0f);
        const float c1   = -10.0f * reps;
        const float c0   = reps;
        const float2* pos2 = (const float2*)pos;
        const int wg = blockIdx.x * (TPB / 32) + warp;   // 0..4159

#pragma unroll
        for (int pass = 0; pass < 2; pass++) {
            const int t = wg + pass * 4160;              // < 8320 always
            const int b = t / TASKS_PER_B;
            const int r = t - b * TASKS_PER_B;
            // unrank r -> (I <= J): row I has (T - I) entries
            int I = (int)(64.5f - sqrtf(fmaf(-2.0f, (float)r, 4160.25f)));
            while ((I + 1) * T - ((I + 1) * I) / 2 <= r) I++;
            while (I * T - (I * (I - 1)) / 2 > r) I--;
            const int base = I * T - (I * (I - 1)) / 2;
            const int J = I + (r - base);
            const bool diag = (I == J);

            const int ib = b * S + I * 32 + lane;
            const int jb = b * S + J * 32 + lane;
            const float2 pi = pos2[ib];
            const float  mi = mass[ib];
            const float2 pj = pos2[jb];
            float xj = pj.x, yj = pj.y, gmj = mass[jb];
            const float xi = pi.x, yi = pi.y;
            const float nGmi = -Gp * mi;

            float fix = 0.f, fiy = 0.f, fjx = 0.f, fjy = 0.f;

#pragma unroll 8
            for (int k = 0; k < 32; k++) {
                const float dx = xj - xi;
                const float dy = yj - yi;
                const float d2 = fmaf(dx, dx, fmaf(dy, dy, SOFT));
                const float u  = rsq(d2);
                const float u3 = (u * u) * u;
                float w = (nGmi * gmj) * u3;           // -(G mi mj)/d^3
                if (__any_sync(0xffffffffu, d2 < CUT2)) {
                    const float d  = d2 * u;
                    const float tt = fmaxf(fmaf(d, c1, c0), 0.0f);
                    w = fmaf(tt * rcp(fmaf(d2, d, EPSF)), u, w);
                }
                fix = fmaf(w, dx, fix);
                fiy = fmaf(w, dy, fiy);
                fjx = fmaf(-w, dx, fjx);               // Newton's 3rd law
                fjy = fmaf(-w, dy, fjy);
                // rotate j-side data + accumulators one lane
                xj  = __shfl_sync(0xffffffffu, xj,  lane + 1);
                yj  = __shfl_sync(0xffffffffu, yj,  lane + 1);
                gmj = __shfl_sync(0xffffffffu, gmj, lane + 1);
                fjx = __shfl_sync(0xffffffffu, fjx, lane + 1);
                fjy = __shfl_sync(0xffffffffu, fjy, lane + 1);
            }
            // after 32 rotations, lane L holds fj for j = J*32 + L
            const int gI = b * T + I;
            const int gJ = b * T + J;
            g_acc[(gI * T + J) * 32 + lane] = make_float2(fix, fiy);
            if (!diag)
                g_acc[(gJ * T + I) * 32 + lane] = make_float2(fjx, fjy);
        }
    } else {
        // =================== LOSS PARTIAL ===================
        __shared__ float wsh[WMAX * 8];
        __shared__ float lred[TPB / 32][8];
        const int lb = blockIdx.x - FBLK;
        if (tid < W * 8) wsh[tid] = wells[tid];
        __syncthreads();

        float s1 = 0.f, s2 = 0.f, s3 = 0.f, s4 = 0.f, s5 = 0.f, s6 = 0.f, s7 = 0.f;
        const int stride = LBL * TPB;

        for (int i = lb * TPB + tid; i < N; i += stride) {
            float2 p = ((const float2*)pos)[i];
            float2 q = ((const float2*)pp2d)[i];
            float dx = p.x - q.x, dy = p.y - q.y;
            float d2 = fmaf(dx, dx, dy * dy);
            float m = mass[i];
            s1 = fmaf(m * pmass[i], rsq(d2), s1);   // eps vs dist: <=1e-6 rel
            s6 += m;
            float2 v = ((const float2*)vel)[i];
            s7 = fmaf(v.x, v.x, fmaf(v.y, v.y, s7));

            float4 a  = ((const float4*)pos8)[i * 2];
            float4 b4 = ((const float4*)pos8)[i * 2 + 1];
            s3 += mind2_row(a, b4, wsh, W);
            a  = ((const float4*)pp8)[i * 2];
            b4 = ((const float4*)pp8)[i * 2 + 1];
            s4 += mind2_row(a, b4, wsh, W);
        }

        for (int n = lb * TPB + tid; n < NK; n += stride) {
            float2 p = ((const float2*)pos)[n / KNEG];
            float2 q = ((const float2*)np2d)[n];
            float dx = p.x - q.x, dy = p.y - q.y;
            float d2 = fmaf(dx, dx, dy * dy);
            s2 = fmaf(emass[n] * nmass[n], rsq(d2), s2);

            float4 a  = ((const float4*)np8)[n * 2];
            float4 b4 = ((const float4*)np8)[n * 2 + 1];
            s5 += mind2_row(a, b4, wsh, W);
        }

        float vals[7] = {s1, s2, s3, s4, s5, s6, s7};
#pragma unroll
        for (int k = 0; k < 7; k++) {
#pragma unroll
            for (int off = 16; off > 0; off >>= 1)
                vals[k] += __shfl_down_sync(0xffffffffu, vals[k], off);
        }
        if (lane == 0) {
#pragma unroll
            for (int k = 0; k < 7; k++) lred[warp][k] = vals[k];
        }
        __syncthreads();
        if (warp == 0) {
#pragma unroll
            for (int k = 0; k < 7; k++) {
                float v = (lane < TPB / 32) ? lred[lane][k] : 0.0f;
#pragma unroll
                for (int off = 8; off > 0; off >>= 1)
                    v += __shfl_down_sync(0xffffffffu, v, off);
                if (lane == 0) g_lpart[lb * 8 + k] = v;
            }
        }
    }
}

// ---------------------------------------------------------------------------
// Kernel 2: per-tile reduce, 256 blocks x 256 threads (8 warps per tile).
// Thread (grp = tid>>5, lane): sums slots {grp + 8k} for k<8, coalesced
// 256B segments, 8-deep MLP per thread x 8 warps. smem tree, then write.
// Loss final in block 0 (g_lpart written by kernel 1).
// ---------------------------------------------------------------------------
__global__ __launch_bounds__(256)
void reduce_kernel(float* __restrict__ out,
                   const float* __restrict__ G_,
                   const float* __restrict__ ws_)
{
    __shared__ float2 sm[8][32];
    const int tile = blockIdx.x;                 // 0..255
    const int lane = threadIdx.x & 31;
    const int grp  = threadIdx.x >> 5;           // 0..7
    const float2* basep = g_acc + tile * (T * 32) + lane;

    float fx = 0.0f, fy = 0.0f;
#pragma unroll
    for (int k = 0; k < 8; k++) {
        const float2 v = basep[(grp + 8 * k) * 32];
        fx += v.x;
        fy += v.y;
    }
    sm[grp][lane] = make_float2(fx, fy);
    __syncthreads();

    if (grp == 0) {
        float sx = 0.0f, sy = 0.0f;
#pragma unroll
        for (int q = 0; q < 8; q++) {
            sx += sm[q][lane].x;
            sy += sm[q][lane].y;
        }
        ((float2*)out)[tile * 32 + lane] = make_float2(sx, sy);
    }

    if (blockIdx.x == 0 && threadIdx.x >= 32 && threadIdx.x < 64) {
        // warp 1 handles the loss final (independent of the tile reduce)
        float s[7];
#pragma unroll
        for (int k = 0; k < 7; k++) {
            float v = (lane < LBL) ? g_lpart[lane * 8 + k] : 0.0f;
            if (lane + 32 < LBL) v += g_lpart[(lane + 32) * 8 + k];
#pragma unroll
            for (int off = 16; off > 0; off >>= 1)
                v += __shfl_down_sync(0xffffffffu, v, off);
            s[k] = v;
        }
        if (lane == 0) {
            const float Gp = fmaxf(G_[0], 0.0f);
            const float ws = fmaxf(ws_[0], 0.0f);
            const float S1 = s[0], S2 = s[1], S3 = s[2], S4 = s[3],
                        S5 = s[4], S6 = s[5], S7 = s[6];
            const float U_pos = -Gp * (S1 / (float)N) +
                                ws * (S3 + S4) / (2.0f * (float)N);
            const float U_neg = -Gp * (S2 / (float)NK) +
                                ws * ((float)KNEG * S3 + S5) / (2.0f * (float)NK);
            // entropy term cancels in F_pos - F_neg
            const float fe = fmaxf(1.0f + U_pos - U_neg, 0.0f);
            const float ke = 1e-3f * 0.5f * (S6 / (float)N) * (S7 / (float)N);
            out[N * 2] = fe + ke;
        }
    }
}

// ---------------------------------------------------------------------------
extern "C" void kernel_launch(void* const* d_in, const int* in_sizes, int n_in,
                              void* d_out, int out_size)
{
    const float* positions_2d = (const float*)d_in[0];
    const float* masses       = (const float*)d_in[1];
    const float* vel_2d       = (const float*)d_in[2];
    const float* pos_8d       = (const float*)d_in[3];
    const float* pos_pos_2d   = (const float*)d_in[4];
    const float* pos_pos_8d   = (const float*)d_in[5];
    const float* positive_m   = (const float*)d_in[6];
    const float* neg_pos_2d   = (const float*)d_in[7];
    const float* neg_pos_8d   = (const float*)d_in[8];
    const float* neg_masses   = (const float*)d_in[9];
    const float* exp_masses   = (const float*)d_in[10];
    const float* G            = (const float*)d_in[11];
    const float* rep_strength = (const float*)d_in[12];
    const float* well_centers = (const float*)d_in[13];
    const float* well_str     = (const float*)d_in[14];
    // temperature (15) / entropy_coeff (16) unused: entropy cancels.

    const int W = in_sizes[13] / 8;
    float* out = (float*)d_out;

    force_loss_kernel<<<TOTAL, TPB>>>(positions_2d, masses, vel_2d, pos_8d,
                                      pos_pos_2d, pos_pos_8d, positive_m,
                                      neg_pos_2d, neg_pos_8d, neg_masses,
                                      exp_masses, well_centers,
                                      G, rep_strength, W);
    reduce_kernel<<<256, 256>>>(out, G, well_str);
}